// round 13
// baseline (speedup 1.0000x reference)
#include <cuda_runtime.h>
#include <cuda_bf16.h>
#include <math.h>
#include <stdint.h>

// Problem constants
#define BB    8
#define SS    512
#define DD    1024
#define NBLK  8
#define KSEL  4
#define MM    (BB*SS)          // 4096
#define BSD   (BB*SS*DD)       // 4,194,304

// GEMM: CTA 128x128, K-chunk 64, 8 warps (2Mx4N), 3-stage cp.async pipeline
#define STAGE 65536            // Ahi16K + Alo16K + Bhi16K + Blo16K
#define GEMM_SMEM (3*STAGE)    // 196608

// Weight regions (elements) in transposed split-bf16 buffers
#define OFF_CATTN 0ull
#define OFF_CFF1  8388608ull
#define OFF_CFF2  25165824ull
#define OFF_BATTN 41943040ull
#define OFF_BFF1  50331648ull
#define OFF_BFF2  58720256ull
#define OFF_CROSS 67108864ull
#define WTOT      69206016ull

// ---------------- scratch (no cudaMalloc allowed) ----------------
__device__ float g_cmean[BB*DD];
__device__ float g_bmean[BB*DD];
__device__ float g_gate_c[NBLK*DD];
__device__ float g_te_c[NBLK*DD];
__device__ float g_gate_b[NBLK*DD];
__device__ float g_te_b[NBLK*DD];
__device__ int   g_ctop[KSEL];
__device__ int   g_btop[KSEL];
__device__ __nv_bfloat16 g_whi[WTOT];      // transposed weights [N,K] hi
__device__ __nv_bfloat16 g_wlo[WTOT];      // lo
__device__ __nv_bfloat16 g_lnhi[2*BSD];    // LN outputs: c @0, b @BSD
__device__ __nv_bfloat16 g_lnlo[2*BSD];
__device__ __nv_bfloat16 g_ffhi[2*BSD];    // c-ff1 output (M x 2048)
__device__ __nv_bfloat16 g_fflo[2*BSD];
__device__ __nv_bfloat16 g_fbhi[BSD];      // b-ff1 output (M x 1024)
__device__ __nv_bfloat16 g_fblo[BSD];
__device__ __nv_bfloat16 g_xhi[2*BSD];     // cross inputs: c @0, b @BSD
__device__ __nv_bfloat16 g_xlo[2*BSD];

// ---------------- helpers ----------------
__device__ __forceinline__ uint32_t smem_u32(const void* p) {
    uint32_t a;
    asm("{ .reg .u64 t; cvta.to.shared.u64 t, %1; cvt.u32.u64 %0, t; }" : "=r"(a) : "l"(p));
    return a;
}
__device__ __forceinline__ void cp16(uint32_t saddr, const void* g) {
    asm volatile("cp.async.cg.shared.global [%0], [%1], 16;" :: "r"(saddr), "l"(g));
}
__device__ __forceinline__ void cp_commit() { asm volatile("cp.async.commit_group;" ::: "memory"); }
__device__ __forceinline__ void cp_wait0()  { asm volatile("cp.async.wait_group 0;" ::: "memory"); }
__device__ __forceinline__ void cp_wait1()  { asm volatile("cp.async.wait_group 1;" ::: "memory"); }

__device__ __forceinline__ void ldm_x4(uint32_t* r, uint32_t addr) {
    asm volatile("ldmatrix.sync.aligned.m8n8.x4.shared.b16 {%0,%1,%2,%3}, [%4];"
        : "=r"(r[0]), "=r"(r[1]), "=r"(r[2]), "=r"(r[3]) : "r"(addr));
}
__device__ __forceinline__ void mma_bf16(float* c, const uint32_t* a, uint32_t b0, uint32_t b1) {
    asm volatile("mma.sync.aligned.m16n8k16.row.col.f32.bf16.bf16.f32 "
        "{%0,%1,%2,%3}, {%4,%5,%6,%7}, {%8,%9}, {%0,%1,%2,%3};"
        : "+f"(c[0]), "+f"(c[1]), "+f"(c[2]), "+f"(c[3])
        : "r"(a[0]), "r"(a[1]), "r"(a[2]), "r"(a[3]), "r"(b0), "r"(b1));
}
__device__ __forceinline__ uint32_t pack_hi(float a, float b, uint32_t& lo_out) {
    __nv_bfloat16 ha = __float2bfloat16(a);
    __nv_bfloat16 hb = __float2bfloat16(b);
    float la = a - __bfloat162float(ha);
    float lb = b - __bfloat162float(hb);
    __nv_bfloat162 h; h.x = ha; h.y = hb;
    __nv_bfloat162 l; l.x = __float2bfloat16(la); l.y = __float2bfloat16(lb);
    lo_out = *(uint32_t*)&l;
    return *(uint32_t*)&h;
}

// ---------------- job structs ----------------
struct GJob {
    const __nv_bfloat16 *Ahi, *Alo, *A2hi, *A2lo;
    const __nv_bfloat16 *Whi, *Wlo;
    const float *bias;
    float *C;
    __nv_bfloat16 *Chi, *Clo;
    const float *te, *gate, *sig, *resid;
    const int* top;
    int step, N, Kd, mode, gxo, strideA, kswitch;
};
struct LJob {
    const float *x, *g, *b;
    __nv_bfloat16 *yhi, *ylo;
    const int* top;
    int step;
};
struct TRegion {
    const float* src;
    __nv_bfloat16 *dhi, *dlo;
    int Kd, N, gx, gy, blocks;   // gx=N/32, gy=Kd/32, blocks=gx*gy*gz
};
struct TRegs { TRegion r[7]; };

// ---------------- launch 1: mean over seq dim, both inputs ----------------
__global__ void mean_all_kernel(const float* __restrict__ ci, const float* __restrict__ bi) {
    int idx = blockIdx.x * blockDim.x + threadIdx.x;   // 0..2*B*D
    const float* x = (idx < BB * DD) ? ci : bi;
    float* out     = (idx < BB * DD) ? g_cmean : g_bmean;
    int k = (idx < BB * DD) ? idx : idx - BB * DD;
    int b = k / DD, d = k - b * DD;
    const float* p = x + (size_t)b * SS * DD + d;
    float s = 0.f;
#pragma unroll 8
    for (int i = 0; i < SS; ++i) s += p[(size_t)i * DD];
    out[k] = s * (1.f / SS);
}

// ---------------- launch 2: routing (block 0) + gate/te prep (blocks 1..32) ----------------
__global__ void routing_prep_kernel(const float* __restrict__ csw, const float* __restrict__ csb,
                                    const float* __restrict__ bsw, const float* __restrict__ bsb,
                                    const float* __restrict__ c_tg, const float* __restrict__ b_tg,
                                    const float* __restrict__ tor) {
    int tid = threadIdx.x;
    if (blockIdx.x > 0) {
        int i = (blockIdx.x - 1) * 256 + tid;
        if (i < NBLK * DD) {
            float t = tor[i & (DD - 1)];
            float gcv = 1.f / (1.f + expf(-c_tg[i]));
            g_gate_c[i] = gcv; g_te_c[i] = gcv * t;
            float gbv = 1.f / (1.f + expf(-b_tg[i]));
            g_gate_b[i] = gbv; g_te_b[i] = gbv * t;
        }
        return;
    }
    __shared__ float red[256];
    __shared__ float score[NBLK];
    for (int p = 0; p < 2; ++p) {
        const float* mean = p ? g_bmean : g_cmean;
        const float* sw   = p ? bsw : csw;
        const float* sb   = p ? bsb : csb;
        int* top          = p ? g_btop : g_ctop;
        float a[NBLK];
#pragma unroll
        for (int j = 0; j < NBLK; ++j) a[j] = 0.f;
        for (int d = tid; d < DD; d += 256) {
            float m = mean[d];
#pragma unroll
            for (int j = 0; j < NBLK; ++j) a[j] += m * sw[d * NBLK + j];
        }
        for (int j = 0; j < NBLK; ++j) {
            red[tid] = a[j];
            __syncthreads();
            for (int o = 128; o > 0; o >>= 1) {
                if (tid < o) red[tid] += red[tid + o];
                __syncthreads();
            }
            if (tid == 0) score[j] = red[0] + sb[j];
            __syncthreads();
        }
        if (tid == 0) {
            float adj[NBLK]; bool used[NBLK];
            for (int j = 0; j < NBLK; ++j) {
                adj[j] = (1.f / (1.f + expf(-score[j]))) * 0.6f + 0.2f;
                used[j] = false;
            }
            for (int k = 0; k < KSEL; ++k) {
                int best = 0; float bv = -1e30f;
                for (int j = 0; j < NBLK; ++j)
                    if (!used[j] && adj[j] > bv) { bv = adj[j]; best = j; }
                used[best] = true;
                top[k] = best;
            }
        }
        __syncthreads();
    }
}

// ---------------- LN device body (split bf16 out) ----------------
__device__ __forceinline__ void ln_body(const LJob& j, int row, int tid) {
    int blk = j.top[j.step];
    float4 v = ((const float4*)(j.x + (size_t)row * DD))[tid];
    float s = v.x + v.y + v.z + v.w;
    float q = v.x * v.x + v.y * v.y + v.z * v.z + v.w * v.w;
#pragma unroll
    for (int o = 16; o > 0; o >>= 1) {
        s += __shfl_down_sync(0xffffffffu, s, o);
        q += __shfl_down_sync(0xffffffffu, q, o);
    }
    __shared__ float ssum[8], sq[8];
    __shared__ float s_mu, s_r;
    int w = tid >> 5, l = tid & 31;
    if (l == 0) { ssum[w] = s; sq[w] = q; }
    __syncthreads();
    if (tid == 0) {
        float S = 0.f, Q = 0.f;
#pragma unroll
        for (int i = 0; i < 8; ++i) { S += ssum[i]; Q += sq[i]; }
        float mu = S * (1.f / DD);
        float var = Q * (1.f / DD) - mu * mu;
        s_mu = mu; s_r = rsqrtf(var + 1e-5f);
    }
    __syncthreads();
    float mu = s_mu, r = s_r;
    float4 gg = ((const float4*)(j.g + (size_t)blk * DD))[tid];
    float4 bb = ((const float4*)(j.b + (size_t)blk * DD))[tid];
    float o0 = (v.x - mu) * r * gg.x + bb.x;
    float o1 = (v.y - mu) * r * gg.y + bb.y;
    float o2 = (v.z - mu) * r * gg.z + bb.z;
    float o3 = (v.w - mu) * r * gg.w + bb.w;
    uint32_t lo0, lo1;
    uint32_t h0 = pack_hi(o0, o1, lo0);
    uint32_t h1 = pack_hi(o2, o3, lo1);
    ((uint2*)j.yhi)[(size_t)row * 256 + tid] = make_uint2(h0, h1);
    ((uint2*)j.ylo)[(size_t)row * 256 + tid] = make_uint2(lo0, lo1);
}

// ---------------- fused LayerNorm (two jobs) ----------------
__global__ void ln2_kernel(LJob j0, LJob j1) {
    const bool first = blockIdx.x < MM;
    ln_body(first ? j0 : j1, first ? blockIdx.x : blockIdx.x - MM, threadIdx.x);
}

// ---------------- launch 3: fused LN1 (both) + all weight transposes ----------------
__global__ void lntrans_kernel(LJob j0, LJob j1, TRegs regs) {
    int tid = threadIdx.x;
    if (blockIdx.x < 2 * MM) {
        const bool first = blockIdx.x < MM;
        ln_body(first ? j0 : j1, first ? blockIdx.x : blockIdx.x - MM, tid);
        return;
    }
    int idx = blockIdx.x - 2 * MM;
    TRegion R = regs.r[0];
#pragma unroll
    for (int i = 0; i < 7; ++i) {
        if (idx < regs.r[i].blocks) { R = regs.r[i]; break; }
        idx -= regs.r[i].blocks;
    }
    int x = idx % R.gx;
    int rem = idx / R.gx;
    int y = rem % R.gy;
    int z = rem / R.gy;
    const float* src = R.src + (size_t)z * R.Kd * R.N;
    __nv_bfloat16* dhi = R.dhi + (size_t)z * R.Kd * R.N;
    __nv_bfloat16* dlo = R.dlo + (size_t)z * R.Kd * R.N;
    int n0 = x * 32, k0 = y * 32;
    __shared__ float ts[32][33];
    {
        int kk = tid >> 3, nn4 = (tid & 7) * 4;
        float4 v = *(const float4*)(src + (size_t)(k0 + kk) * R.N + n0 + nn4);
        ts[kk][nn4 + 0] = v.x; ts[kk][nn4 + 1] = v.y;
        ts[kk][nn4 + 2] = v.z; ts[kk][nn4 + 3] = v.w;
    }
    __syncthreads();
    {
        int nn = tid >> 3, kk4 = (tid & 7) * 4;
        uint32_t h0, h1, l0, l1;
        h0 = pack_hi(ts[kk4 + 0][nn], ts[kk4 + 1][nn], l0);
        h1 = pack_hi(ts[kk4 + 2][nn], ts[kk4 + 3][nn], l1);
        size_t o = (size_t)(n0 + nn) * R.Kd + k0 + kk4;
        *(uint2*)(dhi + o) = make_uint2(h0, h1);
        *(uint2*)(dlo + o) = make_uint2(l0, l1);
    }
}

// ---------------- split-bf16 GEMM (ldmatrix + mma.sync), 3-stage cp.async ----------------
// Fragment double-buffering: kk+1's ldmatrix issued before kk's MMAs so the
// independent LDSM stream overlaps the HMMA stream within each warp.
__global__ __launch_bounds__(256, 1)
void gemm_mma(GJob j0, GJob j1, int split) {
    extern __shared__ __align__(1024) char smem[];
    const uint32_t sb32 = smem_u32(smem);
    const GJob j = (blockIdx.x < split) ? j0 : j1;
    const int tid = threadIdx.x, lane = tid & 31, wid = tid >> 5;
    const int bm = blockIdx.y * 128;
    const int bn = (blockIdx.x - j.gxo) * 128;
    const int wm = (wid & 1) * 64, wn = (wid >> 1) * 32;
    const int blk = j.top ? j.top[j.step] : 0;
    const int N = j.N, Kd = j.Kd;
    const __nv_bfloat16* Whi = j.Whi + (size_t)blk * N * Kd;
    const __nv_bfloat16* Wlo = j.Wlo + (size_t)blk * N * Kd;
    const float* bias = j.bias ? (j.bias + (size_t)blk * N) : nullptr;
    const float* te   = j.te   ? (j.te   + (size_t)blk * DD) : nullptr;
    const float* gate = j.gate ? (j.gate + (size_t)blk * DD) : nullptr;

    const int lr = tid >> 1, lh = tid & 1;
    const __nv_bfloat16* ahp = j.Ahi + (size_t)(bm + lr) * j.strideA;
    const __nv_bfloat16* alp = j.Alo + (size_t)(bm + lr) * j.strideA;
    const __nv_bfloat16* a2hp = j.A2hi ? j.A2hi + (size_t)(bm + lr) * j.strideA : nullptr;
    const __nv_bfloat16* a2lp = j.A2lo ? j.A2lo + (size_t)(bm + lr) * j.strideA : nullptr;
    const __nv_bfloat16* bhp = Whi + (size_t)(bn + lr) * Kd;
    const __nv_bfloat16* blp = Wlo + (size_t)(bn + lr) * Kd;
    uint32_t c_off[4];
#pragma unroll
    for (int i = 0; i < 4; ++i) {
        int ch = lh * 4 + i;
        c_off[i] = (uint32_t)(lr * 128 + ((ch ^ (lr & 7)) << 4));
    }
    const int nt = Kd >> 6;
    const int ksw = j.kswitch;

    auto issue = [&](int u) {
        int tt = u;
        const __nv_bfloat16 *ah = ahp, *al = alp;
        if (u >= ksw) { tt = u - ksw; ah = a2hp; al = a2lp; }
        uint32_t st = sb32 + (uint32_t)(u % 3) * STAGE;
        const int koA = tt * 64, koB = u * 64;
#pragma unroll
        for (int i = 0; i < 4; ++i) {
            int ce = (lh * 4 + i) * 8;
            cp16(st +         c_off[i], ah  + koA + ce);
            cp16(st + 16384 + c_off[i], al  + koA + ce);
            cp16(st + 32768 + c_off[i], bhp + koB + ce);
            cp16(st + 49152 + c_off[i], blp + koB + ce);
        }
        cp_commit();
    };

    float acc[4][4][4];
#pragma unroll
    for (int mi = 0; mi < 4; ++mi)
#pragma unroll
        for (int ni = 0; ni < 4; ++ni)
#pragma unroll
            for (int q = 0; q < 4; ++q) acc[mi][ni][q] = 0.f;

    issue(0);
    issue(1);

    // precomputed per-fragment smem address components
    const int a_row_base = wm + (lane & 15);
    const int b_mat = lane >> 3;
    const int b_row_base = wn + (b_mat >> 1) * 8 + (lane & 7);

    for (int u = 0; u < nt; ++u) {
        if (u == nt - 1) cp_wait0(); else cp_wait1();
        __syncthreads();
        if (u + 2 < nt) issue(u + 2);
        const uint32_t buf = sb32 + (uint32_t)(u % 3) * STAGE;

        uint32_t ah[2][4][4], al[2][4][4], bh[2][2][4], bl[2][2][4];
        auto ldfrag = [&](int kk, int pb) {
#pragma unroll
            for (int mi = 0; mi < 4; ++mi) {
                int row = a_row_base + mi * 16;
                int ch  = kk * 2 + (lane >> 4);
                uint32_t ad = buf + (uint32_t)(row * 128 + ((ch ^ (row & 7)) << 4));
                ldm_x4(ah[pb][mi], ad);
                ldm_x4(al[pb][mi], ad + 16384);
            }
#pragma unroll
            for (int pr = 0; pr < 2; ++pr) {
                int nrow = b_row_base + pr * 16;
                int ch = kk * 2 + (b_mat & 1);
                uint32_t bd = buf + 32768 + (uint32_t)(nrow * 128 + ((ch ^ (nrow & 7)) << 4));
                ldm_x4(bh[pb][pr], bd);
                ldm_x4(bl[pb][pr], bd + 16384);
            }
        };

        ldfrag(0, 0);
#pragma unroll
        for (int kk = 0; kk < 4; ++kk) {
            const int cur = kk & 1;
            if (kk < 3) ldfrag(kk + 1, cur ^ 1);   // independent prefetch overlaps MMAs
            // pass-ordered MMAs on current fragment buffer
#pragma unroll
            for (int mi = 0; mi < 4; ++mi)
#pragma unroll
                for (int ni = 0; ni < 4; ++ni) {
                    int pr = ni >> 1, o = (ni & 1) * 2;
                    mma_bf16(acc[mi][ni], ah[cur][mi], bh[cur][pr][o], bh[cur][pr][o + 1]);
                }
#pragma unroll
            for (int mi = 0; mi < 4; ++mi)
#pragma unroll
                for (int ni = 0; ni < 4; ++ni) {
                    int pr = ni >> 1, o = (ni & 1) * 2;
                    mma_bf16(acc[mi][ni], ah[cur][mi], bl[cur][pr][o], bl[cur][pr][o + 1]);
                }
#pragma unroll
            for (int mi = 0; mi < 4; ++mi)
#pragma unroll
                for (int ni = 0; ni < 4; ++ni) {
                    int pr = ni >> 1, o = (ni & 1) * 2;
                    mma_bf16(acc[mi][ni], al[cur][mi], bh[cur][pr][o], bh[cur][pr][o + 1]);
                }
        }
    }

    // ---- epilogue ----
    const int g = lane >> 2, tg = lane & 3;
#pragma unroll
    for (int mi = 0; mi < 4; ++mi) {
#pragma unroll
        for (int ni = 0; ni < 4; ++ni) {
            int c = bn + wn + ni * 8 + tg * 2;
#pragma unroll
            for (int h = 0; h < 2; ++h) {
                int r = bm + wm + mi * 16 + g + h * 8;
                size_t off = (size_t)r * N;
                float x0 = acc[mi][ni][h * 2], x1 = acc[mi][ni][h * 2 + 1];
                if (bias) { x0 += bias[c]; x1 += bias[c + 1]; }
                if (j.mode == 2) {
                    x0 = 0.5f * x0 * (1.f + erff(x0 * 0.70710678118654752f));
                    x1 = 0.5f * x1 * (1.f + erff(x1 * 0.70710678118654752f));
                    uint32_t lo, hi = pack_hi(x0, x1, lo);
                    *(uint32_t*)&j.Chi[off + c] = hi;
                    *(uint32_t*)&j.Clo[off + c] = lo;
                } else if (j.mode == 3) {
                    x0 = tanhf(x0); x1 = tanhf(x1);
                    uint32_t lo, hi = pack_hi(x0, x1, lo);
                    *(uint32_t*)&j.Chi[off + c] = hi;
                    *(uint32_t*)&j.Clo[off + c] = lo;
                } else {
                    if (j.mode == 1) {
                        x0 *= (1.f + te[c]);     x1 *= (1.f + te[c + 1]);
                        x0 = j.resid[off + c] + 0.5f * x0;
                        x1 = j.resid[off + c + 1] + 0.5f * x1;
                    } else if (j.mode == 4) {
                        int bidx = r >> 9;
                        x0 += j.sig[(size_t)bidx * DD + c]     * 0.3f * gate[c];
                        x1 += j.sig[(size_t)bidx * DD + c + 1] * 0.3f * gate[c + 1];
                        x0 = j.resid[off + c] + 0.5f * x0;
                        x1 = j.resid[off + c + 1] + 0.5f * x1;
                    }
                    *(float2*)&j.C[off + c] = make_float2(x0, x1);
                    if (j.mode == 4 && j.Chi) {
                        uint32_t lo, hi = pack_hi(x0, x1, lo);
                        *(uint32_t*)&j.Chi[off + c] = hi;
                        *(uint32_t*)&j.Clo[off + c] = lo;
                    }
                }
            }
        }
    }
}

// ---------------- host orchestration ----------------
extern "C" void kernel_launch(void* const* d_in, const int* in_sizes, int n_in,
                              void* d_out, int out_size) {
    const float* ci     = (const float*)d_in[0];
    const float* bi     = (const float*)d_in[1];
    const float* tor    = (const float*)d_in[2];
    const float* cln1g  = (const float*)d_in[3];
    const float* cln1b  = (const float*)d_in[4];
    const float* cattw  = (const float*)d_in[5];
    const float* cattb  = (const float*)d_in[6];
    const float* cln2g  = (const float*)d_in[7];
    const float* cln2b  = (const float*)d_in[8];
    const float* cff1w  = (const float*)d_in[9];
    const float* cff1b  = (const float*)d_in[10];
    const float* cff2w  = (const float*)d_in[11];
    const float* cff2b  = (const float*)d_in[12];
    const float* ctg    = (const float*)d_in[13];
    const float* bln1g  = (const float*)d_in[14];
    const float* bln1b  = (const float*)d_in[15];
    const float* battw  = (const float*)d_in[16];
    const float* battb  = (const float*)d_in[17];
    const float* bln2g  = (const float*)d_in[18];
    const float* bln2b  = (const float*)d_in[19];
    const float* bff1w  = (const float*)d_in[20];
    const float* bff1b  = (const float*)d_in[21];
    const float* bff2w  = (const float*)d_in[22];
    const float* bff2b  = (const float*)d_in[23];
    const float* btg    = (const float*)d_in[24];
    const float* cselw  = (const float*)d_in[25];
    const float* cselb  = (const float*)d_in[26];
    const float* bselw  = (const float*)d_in[27];
    const float* bselb  = (const float*)d_in[28];
    const float* crossw = (const float*)d_in[29];
    const float* crossb = (const float*)d_in[30];

    float* outC = (float*)d_out;
    float* outB = outC + (size_t)BSD;
    float* outF = outC + (size_t)2 * BSD;

    __nv_bfloat16 *whi, *wlo, *lnhi, *lnlo, *ffhi, *fflo, *fbhi, *fblo, *xhi, *xlo;
    int *ctop, *btop;
    float *cmean, *bmean, *gc, *tec, *gb, *teb;
    cudaGetSymbolAddress((void**)&whi,  g_whi);
    cudaGetSymbolAddress((void**)&wlo,  g_wlo);
    cudaGetSymbolAddress((void**)&lnhi, g_lnhi);
    cudaGetSymbolAddress((void**)&lnlo, g_lnlo);
    cudaGetSymbolAddress((void**)&ffhi, g_ffhi);
    cudaGetSymbolAddress((void**)&fflo, g_fflo);
    cudaGetSymbolAddress((void**)&fbhi, g_fbhi);
    cudaGetSymbolAddress((void**)&fblo, g_fblo);
    cudaGetSymbolAddress((void**)&xhi,  g_xhi);
    cudaGetSymbolAddress((void**)&xlo,  g_xlo);
    cudaGetSymbolAddress((void**)&ctop, g_ctop);
    cudaGetSymbolAddress((void**)&btop, g_btop);
    cudaGetSymbolAddress((void**)&cmean, g_cmean);
    cudaGetSymbolAddress((void**)&bmean, g_bmean);
    cudaGetSymbolAddress((void**)&gc,  g_gate_c);
    cudaGetSymbolAddress((void**)&tec, g_te_c);
    cudaGetSymbolAddress((void**)&gb,  g_gate_b);
    cudaGetSymbolAddress((void**)&teb, g_te_b);

    cudaFuncSetAttribute(gemm_mma, cudaFuncAttributeMaxDynamicSharedMemorySize, GEMM_SMEM);

    // launch 1: means
    mean_all_kernel<<<(2 * BB * DD + 255) / 256, 256>>>(ci, bi);
    // launch 2: routing + gate/te prep
    routing_prep_kernel<<<33, 256>>>(cselw, cselb, bselw, bselb, ctg, btg, tor);

    // launch 3: LN1(step 0, both pathways) + all weight transposes
    {
        LJob a{ci, cln1g, cln1b, lnhi, lnlo, ctop, 0};
        LJob b{bi, bln1g, bln1b, lnhi + BSD, lnlo + BSD, btop, 0};
        TRegs R;
        auto T = [&](const float* src, unsigned long long off, int Kd, int N, int gz) {
            TRegion r;
            r.src = src; r.dhi = whi + off; r.dlo = wlo + off;
            r.Kd = Kd; r.N = N; r.gx = N / 32; r.gy = Kd / 32;
            r.blocks = r.gx * r.gy * gz;
            return r;
        };
        R.r[0] = T(cattw,  OFF_CATTN, 1024, 1024, 8);
        R.r[1] = T(cff1w,  OFF_CFF1,  1024, 2048, 8);
        R.r[2] = T(cff2w,  OFF_CFF2,  2048, 1024, 8);
        R.r[3] = T(battw,  OFF_BATTN, 1024, 1024, 8);
        R.r[4] = T(bff1w,  OFF_BFF1,  1024, 1024, 8);
        R.r[5] = T(bff2w,  OFF_BFF2,  1024, 1024, 8);
        R.r[6] = T(crossw, OFF_CROSS, 2048, 1024, 1);
        int tblocks = 0;
        for (int i = 0; i < 7; ++i) tblocks += R.r[i].blocks;
        lntrans_kernel<<<2 * MM + tblocks, 256>>>(a, b, R);
    }

    auto G = [&](const __nv_bfloat16* Ahi, const __nv_bfloat16* Alo,
                 const __nv_bfloat16* W1, const __nv_bfloat16* W2,
                 const float* bias, float* C, __nv_bfloat16* Chi, __nv_bfloat16* Clo,
                 const float* te, const float* gate, const float* sig, const float* resid,
                 const int* top, int step, int N, int Kd, int mode, int gxo) {
        GJob j;
        j.Ahi = Ahi; j.Alo = Alo; j.A2hi = nullptr; j.A2lo = nullptr;
        j.Whi = W1; j.Wlo = W2; j.bias = bias; j.C = C; j.Chi = Chi; j.Clo = Clo;
        j.te = te; j.gate = gate; j.sig = sig; j.resid = resid;
        j.top = top; j.step = step; j.N = N; j.Kd = Kd; j.mode = mode;
        j.gxo = gxo; j.strideA = Kd; j.kswitch = 1 << 30;
        return j;
    };

    for (int s = 0; s < KSEL; ++s) {
        const float* inC = (s == 0) ? ci : outC;
        const float* inB = (s == 0) ? bi : outB;
        // LN1 for s>0 (s==0 done in lntrans_kernel)
        if (s > 0) {
            LJob a{inC, cln1g, cln1b, lnhi, lnlo, ctop, s};
            LJob b{inB, bln1g, bln1b, lnhi + BSD, lnlo + BSD, btop, s};
            ln2_kernel<<<2 * MM, 256>>>(a, b);
        }
        // attn (fused, mode 1)
        {
            GJob a = G(lnhi, lnlo, whi + OFF_CATTN, wlo + OFF_CATTN, cattb, outC, nullptr, nullptr,
                       tec, nullptr, nullptr, inC, ctop, s, 1024, 1024, 1, 0);
            GJob b = G(lnhi + BSD, lnlo + BSD, whi + OFF_BATTN, wlo + OFF_BATTN, battb, outB, nullptr, nullptr,
                       teb, nullptr, nullptr, inB, btop, s, 1024, 1024, 1, 8);
            gemm_mma<<<dim3(16, 32), 256, GEMM_SMEM>>>(a, b, 8);
        }
        // LN2 (fused)
        {
            LJob a{outC, cln2g, cln2b, lnhi, lnlo, ctop, s};
            LJob b{outB, bln2g, bln2b, lnhi + BSD, lnlo + BSD, btop, s};
            ln2_kernel<<<2 * MM, 256>>>(a, b);
        }
        // ff1 (fused): c GELU N=2048, b tanh N=1024
        {
            GJob a = G(lnhi, lnlo, whi + OFF_CFF1, wlo + OFF_CFF1, cff1b, nullptr, ffhi, fflo,
                       nullptr, nullptr, nullptr, nullptr, ctop, s, 2048, 1024, 2, 0);
            GJob b = G(lnhi + BSD, lnlo + BSD, whi + OFF_BFF1, wlo + OFF_BFF1, bff1b, nullptr, fbhi, fblo,
                       nullptr, nullptr, nullptr, nullptr, btop, s, 1024, 1024, 3, 16);
            gemm_mma<<<dim3(24, 32), 256, GEMM_SMEM>>>(a, b, 16);
        }
        // ff2 (fused, mode 4); on last step also emit splits for cross
        {
            bool last = (s == KSEL - 1);
            GJob a = G(ffhi, fflo, whi + OFF_CFF2, wlo + OFF_CFF2, cff2b, outC,
                       last ? xhi : nullptr, last ? xlo : nullptr,
                       nullptr, gc, bmean, outC, ctop, s, 1024, 2048, 4, 0);
            GJob b = G(fbhi, fblo, whi + OFF_BFF2, wlo + OFF_BFF2, bff2b, outB,
                       last ? xhi + BSD : nullptr, last ? xlo + BSD : nullptr,
                       nullptr, gb, cmean, outB, btop, s, 1024, 1024, 4, 8);
            gemm_mma<<<dim3(16, 32), 256, GEMM_SMEM>>>(a, b, 8);
        }
    }

    // cross projection: single K=2048 GEMM, A switches halves at chunk 16
    {
        GJob a = G(xhi, xlo, whi + OFF_CROSS, wlo + OFF_CROSS, crossb, outF, nullptr, nullptr,
                   nullptr, nullptr, nullptr, nullptr, nullptr, 0, 1024, 2048, 0, 0);
        a.A2hi = xhi + BSD; a.A2lo = xlo + BSD;
        a.strideA = 1024; a.kswitch = 16;
        gemm_mma<<<dim3(8, 32), 256, GEMM_SMEM>>>(a, a, 8);
    }
}

// round 15
// speedup vs baseline: 1.2231x; 1.2231x over previous
#include <cuda_runtime.h>
#include <cuda_bf16.h>
#include <math.h>
#include <stdint.h>

// Problem constants
#define BB    8
#define SS    512
#define DD    1024
#define NBLK  8
#define KSEL  4
#define MM    (BB*SS)          // 4096
#define BSD   (BB*SS*DD)       // 4,194,304

// GEMM: CTA 128x128, K-chunk 64, 16 warps (4Mx4N, warp tile 32x32), 3-stage cp.async
#define STAGE 65536            // Ahi16K + Alo16K + Bhi16K + Blo16K
#define GEMM_SMEM (3*STAGE)    // 196608
#define GTHREADS 512

// Weight regions (elements) in transposed split-bf16 buffers
#define OFF_CATTN 0ull
#define OFF_CFF1  8388608ull
#define OFF_CFF2  25165824ull
#define OFF_BATTN 41943040ull
#define OFF_BFF1  50331648ull
#define OFF_BFF2  58720256ull
#define OFF_CROSS 67108864ull
#define WTOT      69206016ull

// ---------------- scratch (no cudaMalloc allowed) ----------------
__device__ float g_cmean[BB*DD];
__device__ float g_bmean[BB*DD];
__device__ float g_gate_c[NBLK*DD];
__device__ float g_te_c[NBLK*DD];
__device__ float g_gate_b[NBLK*DD];
__device__ float g_te_b[NBLK*DD];
__device__ int   g_ctop[KSEL];
__device__ int   g_btop[KSEL];
__device__ __nv_bfloat16 g_whi[WTOT];      // transposed weights [N,K] hi
__device__ __nv_bfloat16 g_wlo[WTOT];      // lo
__device__ __nv_bfloat16 g_lnhi[2*BSD];    // LN outputs: c @0, b @BSD
__device__ __nv_bfloat16 g_lnlo[2*BSD];
__device__ __nv_bfloat16 g_ffhi[2*BSD];    // c-ff1 output (M x 2048)
__device__ __nv_bfloat16 g_fflo[2*BSD];
__device__ __nv_bfloat16 g_fbhi[BSD];      // b-ff1 output (M x 1024)
__device__ __nv_bfloat16 g_fblo[BSD];
__device__ __nv_bfloat16 g_xhi[2*BSD];     // cross inputs: c @0, b @BSD
__device__ __nv_bfloat16 g_xlo[2*BSD];

// ---------------- helpers ----------------
__device__ __forceinline__ uint32_t smem_u32(const void* p) {
    uint32_t a;
    asm("{ .reg .u64 t; cvta.to.shared.u64 t, %1; cvt.u32.u64 %0, t; }" : "=r"(a) : "l"(p));
    return a;
}
__device__ __forceinline__ void cp16(uint32_t saddr, const void* g) {
    asm volatile("cp.async.cg.shared.global [%0], [%1], 16;" :: "r"(saddr), "l"(g));
}
__device__ __forceinline__ void cp_commit() { asm volatile("cp.async.commit_group;" ::: "memory"); }
__device__ __forceinline__ void cp_wait0()  { asm volatile("cp.async.wait_group 0;" ::: "memory"); }
__device__ __forceinline__ void cp_wait1()  { asm volatile("cp.async.wait_group 1;" ::: "memory"); }

__device__ __forceinline__ void ldm_x4(uint32_t* r, uint32_t addr) {
    asm volatile("ldmatrix.sync.aligned.m8n8.x4.shared.b16 {%0,%1,%2,%3}, [%4];"
        : "=r"(r[0]), "=r"(r[1]), "=r"(r[2]), "=r"(r[3]) : "r"(addr));
}
__device__ __forceinline__ void mma_bf16(float* c, const uint32_t* a, uint32_t b0, uint32_t b1) {
    asm volatile("mma.sync.aligned.m16n8k16.row.col.f32.bf16.bf16.f32 "
        "{%0,%1,%2,%3}, {%4,%5,%6,%7}, {%8,%9}, {%0,%1,%2,%3};"
        : "+f"(c[0]), "+f"(c[1]), "+f"(c[2]), "+f"(c[3])
        : "r"(a[0]), "r"(a[1]), "r"(a[2]), "r"(a[3]), "r"(b0), "r"(b1));
}
__device__ __forceinline__ uint32_t pack_hi(float a, float b, uint32_t& lo_out) {
    __nv_bfloat16 ha = __float2bfloat16(a);
    __nv_bfloat16 hb = __float2bfloat16(b);
    float la = a - __bfloat162float(ha);
    float lb = b - __bfloat162float(hb);
    __nv_bfloat162 h; h.x = ha; h.y = hb;
    __nv_bfloat162 l; l.x = __float2bfloat16(la); l.y = __float2bfloat16(lb);
    lo_out = *(uint32_t*)&l;
    return *(uint32_t*)&h;
}

// ---------------- job structs ----------------
struct GJob {
    const __nv_bfloat16 *Ahi, *Alo, *A2hi, *A2lo;
    const __nv_bfloat16 *Whi, *Wlo;
    const float *bias;
    float *C;
    __nv_bfloat16 *Chi, *Clo;
    const float *te, *gate, *sig, *resid;
    const int* top;
    int step, N, Kd, mode, gxo, strideA, kswitch;
};
struct LJob {
    const float *x, *g, *b;
    __nv_bfloat16 *yhi, *ylo;
    const int* top;
    int step;
};
struct TRegion {
    const float* src;
    __nv_bfloat16 *dhi, *dlo;
    int Kd, N, gx, gy, blocks;
};
struct TRegs { TRegion r[7]; };

// ---------------- launch 1: mean over seq dim, both inputs ----------------
__global__ void mean_all_kernel(const float* __restrict__ ci, const float* __restrict__ bi) {
    int idx = blockIdx.x * blockDim.x + threadIdx.x;
    const float* x = (idx < BB * DD) ? ci : bi;
    float* out     = (idx < BB * DD) ? g_cmean : g_bmean;
    int k = (idx < BB * DD) ? idx : idx - BB * DD;
    int b = k / DD, d = k - b * DD;
    const float* p = x + (size_t)b * SS * DD + d;
    float s = 0.f;
#pragma unroll 8
    for (int i = 0; i < SS; ++i) s += p[(size_t)i * DD];
    out[k] = s * (1.f / SS);
}

// ---------------- launch 2: routing (block 0) + gate/te prep ----------------
__global__ void routing_prep_kernel(const float* __restrict__ csw, const float* __restrict__ csb,
                                    const float* __restrict__ bsw, const float* __restrict__ bsb,
                                    const float* __restrict__ c_tg, const float* __restrict__ b_tg,
                                    const float* __restrict__ tor) {
    int tid = threadIdx.x;
    if (blockIdx.x > 0) {
        int i = (blockIdx.x - 1) * 256 + tid;
        if (i < NBLK * DD) {
            float t = tor[i & (DD - 1)];
            float gcv = 1.f / (1.f + expf(-c_tg[i]));
            g_gate_c[i] = gcv; g_te_c[i] = gcv * t;
            float gbv = 1.f / (1.f + expf(-b_tg[i]));
            g_gate_b[i] = gbv; g_te_b[i] = gbv * t;
        }
        return;
    }
    __shared__ float red[256];
    __shared__ float score[NBLK];
    for (int p = 0; p < 2; ++p) {
        const float* mean = p ? g_bmean : g_cmean;
        const float* sw   = p ? bsw : csw;
        const float* sb   = p ? bsb : csb;
        int* top          = p ? g_btop : g_ctop;
        float a[NBLK];
#pragma unroll
        for (int j = 0; j < NBLK; ++j) a[j] = 0.f;
        for (int d = tid; d < DD; d += 256) {
            float m = mean[d];
#pragma unroll
            for (int j = 0; j < NBLK; ++j) a[j] += m * sw[d * NBLK + j];
        }
        for (int j = 0; j < NBLK; ++j) {
            red[tid] = a[j];
            __syncthreads();
            for (int o = 128; o > 0; o >>= 1) {
                if (tid < o) red[tid] += red[tid + o];
                __syncthreads();
            }
            if (tid == 0) score[j] = red[0] + sb[j];
            __syncthreads();
        }
        if (tid == 0) {
            float adj[NBLK]; bool used[NBLK];
            for (int j = 0; j < NBLK; ++j) {
                adj[j] = (1.f / (1.f + expf(-score[j]))) * 0.6f + 0.2f;
                used[j] = false;
            }
            for (int k = 0; k < KSEL; ++k) {
                int best = 0; float bv = -1e30f;
                for (int j = 0; j < NBLK; ++j)
                    if (!used[j] && adj[j] > bv) { bv = adj[j]; best = j; }
                used[best] = true;
                top[k] = best;
            }
        }
        __syncthreads();
    }
}

// ---------------- LN device body (split bf16 out) ----------------
__device__ __forceinline__ void ln_body(const LJob& j, int row, int tid) {
    int blk = j.top[j.step];
    float4 v = ((const float4*)(j.x + (size_t)row * DD))[tid];
    float s = v.x + v.y + v.z + v.w;
    float q = v.x * v.x + v.y * v.y + v.z * v.z + v.w * v.w;
#pragma unroll
    for (int o = 16; o > 0; o >>= 1) {
        s += __shfl_down_sync(0xffffffffu, s, o);
        q += __shfl_down_sync(0xffffffffu, q, o);
    }
    __shared__ float ssum[8], sq[8];
    __shared__ float s_mu, s_r;
    int w = tid >> 5, l = tid & 31;
    if (l == 0) { ssum[w] = s; sq[w] = q; }
    __syncthreads();
    if (tid == 0) {
        float S = 0.f, Q = 0.f;
#pragma unroll
        for (int i = 0; i < 8; ++i) { S += ssum[i]; Q += sq[i]; }
        float mu = S * (1.f / DD);
        float var = Q * (1.f / DD) - mu * mu;
        s_mu = mu; s_r = rsqrtf(var + 1e-5f);
    }
    __syncthreads();
    float mu = s_mu, r = s_r;
    float4 gg = ((const float4*)(j.g + (size_t)blk * DD))[tid];
    float4 bb = ((const float4*)(j.b + (size_t)blk * DD))[tid];
    float o0 = (v.x - mu) * r * gg.x + bb.x;
    float o1 = (v.y - mu) * r * gg.y + bb.y;
    float o2 = (v.z - mu) * r * gg.z + bb.z;
    float o3 = (v.w - mu) * r * gg.w + bb.w;
    uint32_t lo0, lo1;
    uint32_t h0 = pack_hi(o0, o1, lo0);
    uint32_t h1 = pack_hi(o2, o3, lo1);
    ((uint2*)j.yhi)[(size_t)row * 256 + tid] = make_uint2(h0, h1);
    ((uint2*)j.ylo)[(size_t)row * 256 + tid] = make_uint2(lo0, lo1);
}

// ---------------- fused LayerNorm (two jobs) ----------------
__global__ void ln2_kernel(LJob j0, LJob j1) {
    const bool first = blockIdx.x < MM;
    ln_body(first ? j0 : j1, first ? blockIdx.x : blockIdx.x - MM, threadIdx.x);
}

// ---------------- launch 3: fused LN1 (both) + all weight transposes ----------------
__global__ void lntrans_kernel(LJob j0, LJob j1, TRegs regs) {
    int tid = threadIdx.x;
    if (blockIdx.x < 2 * MM) {
        const bool first = blockIdx.x < MM;
        ln_body(first ? j0 : j1, first ? blockIdx.x : blockIdx.x - MM, tid);
        return;
    }
    int idx = blockIdx.x - 2 * MM;
    TRegion R = regs.r[0];
#pragma unroll
    for (int i = 0; i < 7; ++i) {
        if (idx < regs.r[i].blocks) { R = regs.r[i]; break; }
        idx -= regs.r[i].blocks;
    }
    int x = idx % R.gx;
    int rem = idx / R.gx;
    int y = rem % R.gy;
    int z = rem / R.gy;
    const float* src = R.src + (size_t)z * R.Kd * R.N;
    __nv_bfloat16* dhi = R.dhi + (size_t)z * R.Kd * R.N;
    __nv_bfloat16* dlo = R.dlo + (size_t)z * R.Kd * R.N;
    int n0 = x * 32, k0 = y * 32;
    __shared__ float ts[32][33];
    {
        int kk = tid >> 3, nn4 = (tid & 7) * 4;
        float4 v = *(const float4*)(src + (size_t)(k0 + kk) * R.N + n0 + nn4);
        ts[kk][nn4 + 0] = v.x; ts[kk][nn4 + 1] = v.y;
        ts[kk][nn4 + 2] = v.z; ts[kk][nn4 + 3] = v.w;
    }
    __syncthreads();
    {
        int nn = tid >> 3, kk4 = (tid & 7) * 4;
        uint32_t h0, h1, l0, l1;
        h0 = pack_hi(ts[kk4 + 0][nn], ts[kk4 + 1][nn], l0);
        h1 = pack_hi(ts[kk4 + 2][nn], ts[kk4 + 3][nn], l1);
        size_t o = (size_t)(n0 + nn) * R.Kd + k0 + kk4;
        *(uint2*)(dhi + o) = make_uint2(h0, h1);
        *(uint2*)(dlo + o) = make_uint2(l0, l1);
    }
}

// ---------------- split-bf16 GEMM: 512 threads, warp tile 32x32, 3-stage cp.async ----------------
__global__ __launch_bounds__(GTHREADS, 1)
void gemm_mma(GJob j0, GJob j1, int split) {
    extern __shared__ __align__(1024) char smem[];
    const uint32_t sb32 = smem_u32(smem);
    const GJob j = (blockIdx.x < split) ? j0 : j1;
    const int tid = threadIdx.x, lane = tid & 31, wid = tid >> 5;
    const int bm = blockIdx.y * 128;
    const int bn = (blockIdx.x - j.gxo) * 128;
    const int wm = (wid & 3) * 32, wn = (wid >> 2) * 32;   // 4M x 4N warps
    const int blk = j.top ? j.top[j.step] : 0;
    const int N = j.N, Kd = j.Kd;
    const __nv_bfloat16* Whi = j.Whi + (size_t)blk * N * Kd;
    const __nv_bfloat16* Wlo = j.Wlo + (size_t)blk * N * Kd;
    const float* bias = j.bias ? (j.bias + (size_t)blk * N) : nullptr;
    const float* te   = j.te   ? (j.te   + (size_t)blk * DD) : nullptr;
    const float* gate = j.gate ? (j.gate + (size_t)blk * DD) : nullptr;

    // loader mapping: 4 threads per row (128 rows), each covers 2 of 8 16B chunks
    const int lr = tid >> 2, lq = tid & 3;
    const __nv_bfloat16* ahp = j.Ahi + (size_t)(bm + lr) * j.strideA;
    const __nv_bfloat16* alp = j.Alo + (size_t)(bm + lr) * j.strideA;
    const __nv_bfloat16* a2hp = j.A2hi ? j.A2hi + (size_t)(bm + lr) * j.strideA : nullptr;
    const __nv_bfloat16* a2lp = j.A2lo ? j.A2lo + (size_t)(bm + lr) * j.strideA : nullptr;
    const __nv_bfloat16* bhp = Whi + (size_t)(bn + lr) * Kd;
    const __nv_bfloat16* blp = Wlo + (size_t)(bn + lr) * Kd;
    uint32_t c_off[2];
#pragma unroll
    for (int i = 0; i < 2; ++i) {
        int ch = lq * 2 + i;
        c_off[i] = (uint32_t)(lr * 128 + ((ch ^ (lr & 7)) << 4));
    }
    const int nt = Kd >> 6;
    const int ksw = j.kswitch;

    auto issue = [&](int u) {
        int tt = u;
        const __nv_bfloat16 *ah = ahp, *al = alp;
        if (u >= ksw) { tt = u - ksw; ah = a2hp; al = a2lp; }
        uint32_t st = sb32 + (uint32_t)(u % 3) * STAGE;
        const int koA = tt * 64, koB = u * 64;
#pragma unroll
        for (int i = 0; i < 2; ++i) {
            int ce = (lq * 2 + i) * 8;
            cp16(st +         c_off[i], ah  + koA + ce);
            cp16(st + 16384 + c_off[i], al  + koA + ce);
            cp16(st + 32768 + c_off[i], bhp + koB + ce);
            cp16(st + 49152 + c_off[i], blp + koB + ce);
        }
        cp_commit();
    };

    float acc[2][4][4];
#pragma unroll
    for (int mi = 0; mi < 2; ++mi)
#pragma unroll
        for (int ni = 0; ni < 4; ++ni)
#pragma unroll
            for (int q = 0; q < 4; ++q) acc[mi][ni][q] = 0.f;

    issue(0);
    issue(1);

    const int a_row_base = wm + (lane & 15);
    const int b_mat = lane >> 3;
    const int b_row_base = wn + (b_mat >> 1) * 8 + (lane & 7);

    for (int u = 0; u < nt; ++u) {
        if (u == nt - 1) cp_wait0(); else cp_wait1();
        __syncthreads();
        if (u + 2 < nt) issue(u + 2);
        const uint32_t buf = sb32 + (uint32_t)(u % 3) * STAGE;
#pragma unroll
        for (int kk = 0; kk < 4; ++kk) {
            uint32_t ah[2][4], al[2][4], bh[2][4], bl[2][4];
#pragma unroll
            for (int mi = 0; mi < 2; ++mi) {
                int row = a_row_base + mi * 16;
                int ch  = kk * 2 + (lane >> 4);
                uint32_t ad = buf + (uint32_t)(row * 128 + ((ch ^ (row & 7)) << 4));
                ldm_x4(ah[mi], ad);
                ldm_x4(al[mi], ad + 16384);
            }
#pragma unroll
            for (int pr = 0; pr < 2; ++pr) {
                int nrow = b_row_base + pr * 16;
                int ch = kk * 2 + (b_mat & 1);
                uint32_t bd = buf + 32768 + (uint32_t)(nrow * 128 + ((ch ^ (nrow & 7)) << 4));
                ldm_x4(bh[pr], bd);
                ldm_x4(bl[pr], bd + 16384);
            }
            // pass-ordered MMAs (8 per pass)
#pragma unroll
            for (int mi = 0; mi < 2; ++mi)
#pragma unroll
                for (int ni = 0; ni < 4; ++ni) {
                    int pr = ni >> 1, o = (ni & 1) * 2;
                    mma_bf16(acc[mi][ni], ah[mi], bh[pr][o], bh[pr][o + 1]);
                }
#pragma unroll
            for (int mi = 0; mi < 2; ++mi)
#pragma unroll
                for (int ni = 0; ni < 4; ++ni) {
                    int pr = ni >> 1, o = (ni & 1) * 2;
                    mma_bf16(acc[mi][ni], ah[mi], bl[pr][o], bl[pr][o + 1]);
                }
#pragma unroll
            for (int mi = 0; mi < 2; ++mi)
#pragma unroll
                for (int ni = 0; ni < 4; ++ni) {
                    int pr = ni >> 1, o = (ni & 1) * 2;
                    mma_bf16(acc[mi][ni], al[mi], bh[pr][o], bh[pr][o + 1]);
                }
        }
    }

    // ---- epilogue ----
    const int g = lane >> 2, tg = lane & 3;
#pragma unroll
    for (int mi = 0; mi < 2; ++mi) {
#pragma unroll
        for (int ni = 0; ni < 4; ++ni) {
            int c = bn + wn + ni * 8 + tg * 2;
#pragma unroll
            for (int h = 0; h < 2; ++h) {
                int r = bm + wm + mi * 16 + g + h * 8;
                size_t off = (size_t)r * N;
                float x0 = acc[mi][ni][h * 2], x1 = acc[mi][ni][h * 2 + 1];
                if (bias) { x0 += bias[c]; x1 += bias[c + 1]; }
                if (j.mode == 2) {
                    x0 = 0.5f * x0 * (1.f + erff(x0 * 0.70710678118654752f));
                    x1 = 0.5f * x1 * (1.f + erff(x1 * 0.70710678118654752f));
                    uint32_t lo, hi = pack_hi(x0, x1, lo);
                    *(uint32_t*)&j.Chi[off + c] = hi;
                    *(uint32_t*)&j.Clo[off + c] = lo;
                } else if (j.mode == 3) {
                    x0 = tanhf(x0); x1 = tanhf(x1);
                    uint32_t lo, hi = pack_hi(x0, x1, lo);
                    *(uint32_t*)&j.Chi[off + c] = hi;
                    *(uint32_t*)&j.Clo[off + c] = lo;
                } else {
                    if (j.mode == 1) {
                        x0 *= (1.f + te[c]);     x1 *= (1.f + te[c + 1]);
                        x0 = j.resid[off + c] + 0.5f * x0;
                        x1 = j.resid[off + c + 1] + 0.5f * x1;
                    } else if (j.mode == 4) {
                        int bidx = r >> 9;
                        x0 += j.sig[(size_t)bidx * DD + c]     * 0.3f * gate[c];
                        x1 += j.sig[(size_t)bidx * DD + c + 1] * 0.3f * gate[c + 1];
                        x0 = j.resid[off + c] + 0.5f * x0;
                        x1 = j.resid[off + c + 1] + 0.5f * x1;
                    }
                    *(float2*)&j.C[off + c] = make_float2(x0, x1);
                    if (j.mode == 4 && j.Chi) {
                        uint32_t lo, hi = pack_hi(x0, x1, lo);
                        *(uint32_t*)&j.Chi[off + c] = hi;
                        *(uint32_t*)&j.Clo[off + c] = lo;
                    }
                }
            }
        }
    }
}

// ---------------- host orchestration ----------------
extern "C" void kernel_launch(void* const* d_in, const int* in_sizes, int n_in,
                              void* d_out, int out_size) {
    const float* ci     = (const float*)d_in[0];
    const float* bi     = (const float*)d_in[1];
    const float* tor    = (const float*)d_in[2];
    const float* cln1g  = (const float*)d_in[3];
    const float* cln1b  = (const float*)d_in[4];
    const float* cattw  = (const float*)d_in[5];
    const float* cattb  = (const float*)d_in[6];
    const float* cln2g  = (const float*)d_in[7];
    const float* cln2b  = (const float*)d_in[8];
    const float* cff1w  = (const float*)d_in[9];
    const float* cff1b  = (const float*)d_in[10];
    const float* cff2w  = (const float*)d_in[11];
    const float* cff2b  = (const float*)d_in[12];
    const float* ctg    = (const float*)d_in[13];
    const float* bln1g  = (const float*)d_in[14];
    const float* bln1b  = (const float*)d_in[15];
    const float* battw  = (const float*)d_in[16];
    const float* battb  = (const float*)d_in[17];
    const float* bln2g  = (const float*)d_in[18];
    const float* bln2b  = (const float*)d_in[19];
    const float* bff1w  = (const float*)d_in[20];
    const float* bff1b  = (const float*)d_in[21];
    const float* bff2w  = (const float*)d_in[22];
    const float* bff2b  = (const float*)d_in[23];
    const float* btg    = (const float*)d_in[24];
    const float* cselw  = (const float*)d_in[25];
    const float* cselb  = (const float*)d_in[26];
    const float* bselw  = (const float*)d_in[27];
    const float* bselb  = (const float*)d_in[28];
    const float* crossw = (const float*)d_in[29];
    const float* crossb = (const float*)d_in[30];

    float* outC = (float*)d_out;
    float* outB = outC + (size_t)BSD;
    float* outF = outC + (size_t)2 * BSD;

    __nv_bfloat16 *whi, *wlo, *lnhi, *lnlo, *ffhi, *fflo, *fbhi, *fblo, *xhi, *xlo;
    int *ctop, *btop;
    float *cmean, *bmean, *gc, *tec, *gb, *teb;
    cudaGetSymbolAddress((void**)&whi,  g_whi);
    cudaGetSymbolAddress((void**)&wlo,  g_wlo);
    cudaGetSymbolAddress((void**)&lnhi, g_lnhi);
    cudaGetSymbolAddress((void**)&lnlo, g_lnlo);
    cudaGetSymbolAddress((void**)&ffhi, g_ffhi);
    cudaGetSymbolAddress((void**)&fflo, g_fflo);
    cudaGetSymbolAddress((void**)&fbhi, g_fbhi);
    cudaGetSymbolAddress((void**)&fblo, g_fblo);
    cudaGetSymbolAddress((void**)&xhi,  g_xhi);
    cudaGetSymbolAddress((void**)&xlo,  g_xlo);
    cudaGetSymbolAddress((void**)&ctop, g_ctop);
    cudaGetSymbolAddress((void**)&btop, g_btop);
    cudaGetSymbolAddress((void**)&cmean, g_cmean);
    cudaGetSymbolAddress((void**)&bmean, g_bmean);
    cudaGetSymbolAddress((void**)&gc,  g_gate_c);
    cudaGetSymbolAddress((void**)&tec, g_te_c);
    cudaGetSymbolAddress((void**)&gb,  g_gate_b);
    cudaGetSymbolAddress((void**)&teb, g_te_b);

    cudaFuncSetAttribute(gemm_mma, cudaFuncAttributeMaxDynamicSharedMemorySize, GEMM_SMEM);

    mean_all_kernel<<<(2 * BB * DD + 255) / 256, 256>>>(ci, bi);
    routing_prep_kernel<<<33, 256>>>(cselw, cselb, bselw, bselb, ctg, btg, tor);

    // launch 3: LN1(step 0) + all weight transposes
    {
        LJob a{ci, cln1g, cln1b, lnhi, lnlo, ctop, 0};
        LJob b{bi, bln1g, bln1b, lnhi + BSD, lnlo + BSD, btop, 0};
        TRegs R;
        auto T = [&](const float* src, unsigned long long off, int Kd, int N, int gz) {
            TRegion r;
            r.src = src; r.dhi = whi + off; r.dlo = wlo + off;
            r.Kd = Kd; r.N = N; r.gx = N / 32; r.gy = Kd / 32;
            r.blocks = r.gx * r.gy * gz;
            return r;
        };
        R.r[0] = T(cattw,  OFF_CATTN, 1024, 1024, 8);
        R.r[1] = T(cff1w,  OFF_CFF1,  1024, 2048, 8);
        R.r[2] = T(cff2w,  OFF_CFF2,  2048, 1024, 8);
        R.r[3] = T(battw,  OFF_BATTN, 1024, 1024, 8);
        R.r[4] = T(bff1w,  OFF_BFF1,  1024, 1024, 8);
        R.r[5] = T(bff2w,  OFF_BFF2,  1024, 1024, 8);
        R.r[6] = T(crossw, OFF_CROSS, 2048, 1024, 1);
        int tblocks = 0;
        for (int i = 0; i < 7; ++i) tblocks += R.r[i].blocks;
        lntrans_kernel<<<2 * MM + tblocks, 256>>>(a, b, R);
    }

    auto G = [&](const __nv_bfloat16* Ahi, const __nv_bfloat16* Alo,
                 const __nv_bfloat16* W1, const __nv_bfloat16* W2,
                 const float* bias, float* C, __nv_bfloat16* Chi, __nv_bfloat16* Clo,
                 const float* te, const float* gate, const float* sig, const float* resid,
                 const int* top, int step, int N, int Kd, int mode, int gxo) {
        GJob j;
        j.Ahi = Ahi; j.Alo = Alo; j.A2hi = nullptr; j.A2lo = nullptr;
        j.Whi = W1; j.Wlo = W2; j.bias = bias; j.C = C; j.Chi = Chi; j.Clo = Clo;
        j.te = te; j.gate = gate; j.sig = sig; j.resid = resid;
        j.top = top; j.step = step; j.N = N; j.Kd = Kd; j.mode = mode;
        j.gxo = gxo; j.strideA = Kd; j.kswitch = 1 << 30;
        return j;
    };

    for (int s = 0; s < KSEL; ++s) {
        const float* inC = (s == 0) ? ci : outC;
        const float* inB = (s == 0) ? bi : outB;
        if (s > 0) {
            LJob a{inC, cln1g, cln1b, lnhi, lnlo, ctop, s};
            LJob b{inB, bln1g, bln1b, lnhi + BSD, lnlo + BSD, btop, s};
            ln2_kernel<<<2 * MM, 256>>>(a, b);
        }
        // attn (fused, mode 1)
        {
            GJob a = G(lnhi, lnlo, whi + OFF_CATTN, wlo + OFF_CATTN, cattb, outC, nullptr, nullptr,
                       tec, nullptr, nullptr, inC, ctop, s, 1024, 1024, 1, 0);
            GJob b = G(lnhi + BSD, lnlo + BSD, whi + OFF_BATTN, wlo + OFF_BATTN, battb, outB, nullptr, nullptr,
                       teb, nullptr, nullptr, inB, btop, s, 1024, 1024, 1, 8);
            gemm_mma<<<dim3(16, 32), GTHREADS, GEMM_SMEM>>>(a, b, 8);
        }
        // LN2 (fused)
        {
            LJob a{outC, cln2g, cln2b, lnhi, lnlo, ctop, s};
            LJob b{outB, bln2g, bln2b, lnhi + BSD, lnlo + BSD, btop, s};
            ln2_kernel<<<2 * MM, 256>>>(a, b);
        }
        // ff1 (fused): c GELU N=2048, b tanh N=1024
        {
            GJob a = G(lnhi, lnlo, whi + OFF_CFF1, wlo + OFF_CFF1, cff1b, nullptr, ffhi, fflo,
                       nullptr, nullptr, nullptr, nullptr, ctop, s, 2048, 1024, 2, 0);
            GJob b = G(lnhi + BSD, lnlo + BSD, whi + OFF_BFF1, wlo + OFF_BFF1, bff1b, nullptr, fbhi, fblo,
                       nullptr, nullptr, nullptr, nullptr, btop, s, 1024, 1024, 3, 16);
            gemm_mma<<<dim3(24, 32), GTHREADS, GEMM_SMEM>>>(a, b, 16);
        }
        // ff2 (fused, mode 4); on last step also emit splits for cross
        {
            bool last = (s == KSEL - 1);
            GJob a = G(ffhi, fflo, whi + OFF_CFF2, wlo + OFF_CFF2, cff2b, outC,
                       last ? xhi : nullptr, last ? xlo : nullptr,
                       nullptr, gc, bmean, outC, ctop, s, 1024, 2048, 4, 0);
            GJob b = G(fbhi, fblo, whi + OFF_BFF2, wlo + OFF_BFF2, bff2b, outB,
                       last ? xhi + BSD : nullptr, last ? xlo + BSD : nullptr,
                       nullptr, gb, cmean, outB, btop, s, 1024, 1024, 4, 8);
            gemm_mma<<<dim3(16, 32), GTHREADS, GEMM_SMEM>>>(a, b, 8);
        }
    }

    // cross projection: single K=2048 GEMM, A switches halves at chunk 16
    {
        GJob a = G(xhi, xlo, whi + OFF_CROSS, wlo + OFF_CROSS, crossb, outF, nullptr, nullptr,
                   nullptr, nullptr, nullptr, nullptr, nullptr, 0, 1024, 2048, 0, 0);
        a.A2hi = xhi + BSD; a.A2lo = xlo + BSD;
        a.strideA = 1024; a.kswitch = 16;
        gemm_mma<<<dim3(8, 32), GTHREADS, GEMM_SMEM>>>(a, a, 8);
    }
}